// round 5
// baseline (speedup 1.0000x reference)
#include <cuda_runtime.h>
#include <cuda_bf16.h>
#include <cstdint>

// AddRadiusEdgeIndex: N=8192 points in [0,10]^3, r=1.
// out[0 : N*N)     = masked_dist2 (float32)
// out[N*N : 2*N*N) = edge_mask as 0.0/1.0 float32
//
// Single fused kernel: block = 64 rows x 2048 cols tile, 8 cols/thread.
// Points loaded directly from pos (L2-resident), |p|^2 via exact reference
// fma chain, dist2 via exact rn ops (no re-contraction).
// Stores: 2x st.global.cs.v8.f32 (256-bit) per thread per row. 536 MB total
// -> pure HBM-write-bound.

#define NPTS  8192
#define ITILE 64
#define JTILE 2048   // 256 threads * 8 cols

__device__ __forceinline__ void stg_cs_v8(float* p, const float* v) {
#if __CUDA_ARCH__ >= 1000
    asm volatile(
        "st.global.cs.v8.f32 [%0], {%1, %2, %3, %4, %5, %6, %7, %8};"
        :: "l"(p),
           "f"(v[0]), "f"(v[1]), "f"(v[2]), "f"(v[3]),
           "f"(v[4]), "f"(v[5]), "f"(v[6]), "f"(v[7])
        : "memory");
#else
    __stcs(reinterpret_cast<float4*>(p),     make_float4(v[0], v[1], v[2], v[3]));
    __stcs(reinterpret_cast<float4*>(p) + 1, make_float4(v[4], v[5], v[6], v[7]));
#endif
}

__global__ void __launch_bounds__(256) radius_kernel(const float* __restrict__ pos,
                                                     float* __restrict__ out) {
    __shared__ float4 s_pi[ITILE];

    const int i0 = blockIdx.y * ITILE;
    const int j0 = blockIdx.x * JTILE + threadIdx.x * 8;

    // Load this thread's 8 column points; compute sq with the exact fma chain.
    float4 pj[8];
#pragma unroll
    for (int k = 0; k < 8; k++) {
        const float x = pos[3 * (j0 + k) + 0];
        const float y = pos[3 * (j0 + k) + 1];
        const float z = pos[3 * (j0 + k) + 2];
        float s = __fmul_rn(x, x);
        s = __fmaf_rn(y, y, s);
        s = __fmaf_rn(z, z, s);
        pj[k] = make_float4(x, y, z, s);
    }

    // Row tile into smem: threads 0..63 each build one pi.
    if (threadIdx.x < ITILE) {
        const int i = i0 + threadIdx.x;
        const float x = pos[3 * i + 0];
        const float y = pos[3 * i + 1];
        const float z = pos[3 * i + 2];
        float s = __fmul_rn(x, x);
        s = __fmaf_rn(y, y, s);
        s = __fmaf_rn(z, z, s);
        s_pi[threadIdx.x] = make_float4(x, y, z, s);
    }
    __syncthreads();

    float* od = out + (size_t)i0 * NPTS + j0;
    float* om = od + (size_t)NPTS * NPTS;

#pragma unroll 4
    for (int r = 0; r < ITILE; r++) {
        const float4 pi = s_pi[r];  // broadcast LDS, conflict-free

        float d[8], m[8];
#pragma unroll
        for (int k = 0; k < 8; k++) {
            float dot = __fmul_rn(pi.x, pj[k].x);
            dot = __fmaf_rn(pi.y, pj[k].y, dot);
            dot = __fmaf_rn(pi.z, pj[k].z, dot);
            // (sq_i + sq_j) - 2*dot : exact rounding order, no fma contraction
            float dd = __fsub_rn(__fadd_rn(pi.w, pj[k].w), __fmul_rn(2.0f, dot));
            dd = fmaxf(dd, 0.0f);
            const bool e = (dd <= 1.0f);
            d[k] = e ? dd : 0.0f;
            m[k] = e ? 1.0f : 0.0f;
        }

        stg_cs_v8(od, d);
        stg_cs_v8(om, m);
        od += NPTS;
        om += NPTS;
    }
}

extern "C" void kernel_launch(void* const* d_in, const int* in_sizes, int n_in,
                              void* d_out, int out_size) {
    const float* pos = (const float*)d_in[0];
    float* out = (float*)d_out;

    dim3 grid(NPTS / JTILE, NPTS / ITILE);  // (4, 128)
    radius_kernel<<<grid, 256>>>(pos, out);
}

// round 6
// speedup vs baseline: 1.1732x; 1.1732x over previous
#include <cuda_runtime.h>
#include <cuda_bf16.h>
#include <cstdint>

// AddRadiusEdgeIndex: N=8192 points in [0,10]^3, r=1.
// out[0 : N*N)     = masked_dist2 (float32)
// out[N*N : 2*N*N) = edge_mask as 0.0/1.0 float32
//
// Single fused kernel: block = 64 rows x 2048 cols tile, 512 threads,
// 4 cols/thread (regs ~40 -> high residency; store-MLP bound kernel).
// |p|^2 via exact reference fma chain, dist2 via exact rn ops.
// Stores: 2x STG.128 streaming per thread per row. 536 MB -> HBM-write-bound.

#define NPTS  8192
#define ITILE 64
#define JTILE 2048   // 512 threads * 4 cols
#define TPB   512

__global__ void __launch_bounds__(TPB) radius_kernel(const float* __restrict__ pos,
                                                     float* __restrict__ out) {
    __shared__ float4 s_pi[ITILE];

    const int i0 = blockIdx.y * ITILE;
    const int j0 = blockIdx.x * JTILE + threadIdx.x * 4;

    // Load this thread's 4 column points; compute sq with the exact fma chain.
    float4 pj[4];
#pragma unroll
    for (int k = 0; k < 4; k++) {
        const float x = pos[3 * (j0 + k) + 0];
        const float y = pos[3 * (j0 + k) + 1];
        const float z = pos[3 * (j0 + k) + 2];
        float s = __fmul_rn(x, x);
        s = __fmaf_rn(y, y, s);
        s = __fmaf_rn(z, z, s);
        pj[k] = make_float4(x, y, z, s);
    }

    // Row tile into smem: threads 0..63 each build one pi.
    if (threadIdx.x < ITILE) {
        const int i = i0 + threadIdx.x;
        const float x = pos[3 * i + 0];
        const float y = pos[3 * i + 1];
        const float z = pos[3 * i + 2];
        float s = __fmul_rn(x, x);
        s = __fmaf_rn(y, y, s);
        s = __fmaf_rn(z, z, s);
        s_pi[threadIdx.x] = make_float4(x, y, z, s);
    }
    __syncthreads();

    float* od = out + (size_t)i0 * NPTS + j0;
    float* om = od + (size_t)NPTS * NPTS;

#pragma unroll 4
    for (int r = 0; r < ITILE; r++) {
        const float4 pi = s_pi[r];  // broadcast LDS, conflict-free

        float d[4], m[4];
#pragma unroll
        for (int k = 0; k < 4; k++) {
            float dot = __fmul_rn(pi.x, pj[k].x);
            dot = __fmaf_rn(pi.y, pj[k].y, dot);
            dot = __fmaf_rn(pi.z, pj[k].z, dot);
            // (sq_i + sq_j) - 2*dot : exact rounding order, no fma contraction
            float dd = __fsub_rn(__fadd_rn(pi.w, pj[k].w), __fmul_rn(2.0f, dot));
            dd = fmaxf(dd, 0.0f);
            const bool e = (dd <= 1.0f);
            d[k] = e ? dd : 0.0f;
            m[k] = e ? 1.0f : 0.0f;
        }

        __stcs(reinterpret_cast<float4*>(od), make_float4(d[0], d[1], d[2], d[3]));
        __stcs(reinterpret_cast<float4*>(om), make_float4(m[0], m[1], m[2], m[3]));
        od += NPTS;
        om += NPTS;
    }
}

extern "C" void kernel_launch(void* const* d_in, const int* in_sizes, int n_in,
                              void* d_out, int out_size) {
    const float* pos = (const float*)d_in[0];
    float* out = (float*)d_out;

    dim3 grid(NPTS / JTILE, NPTS / ITILE);  // (4, 128)
    radius_kernel<<<grid, TPB>>>(pos, out);
}